// round 13
// baseline (speedup 1.0000x reference)
#include <cuda_runtime.h>
#include <cuda_fp16.h>
#include <cstdint>

#define Ld    2
#define Hd    2048
#define OUTD  1024
#define Bd    64
#define Td    256
#define NCTA  128
#define THRM  512   // 16 warps
#define THRP  256
#define KC    128
#define ST    6     // ring stages

#define APAD  72
#define GPAD  68
#define PPAD  68
#define WPAD  136   // proj path only

// lstm_main smem: 6-stage ring (W 16K + B 18K per stage); sP/sG alias stages 0-1
#define WB        16384
#define STB       (WB + KC * APAD * 2)       // 34816
#define SMEM_MAIN (ST * STB)                 // 208896
#define SP_OFF    0                          // 3 x 64 x PPAD x 4 = 52224
#define SG_OFF    52224                      // 64 x GPAD x 4 = 17408 (ends at 69632 = 2*STB)

// proj smem
#define SMEM_A_OLD (2 * KC * APAD * 2)
#define SMEM_W_OLD (2 * 64 * WPAD * 2)
#define SMEM_G_OLD (64 * GPAD * 4)
#define SMEM_PROJ  (SMEM_W_OLD + SMEM_A_OLD + SMEM_G_OLD)

// ----------------------------- device globals ------------------------------
// W fragments per (l,ct,chunk): [wm2*wk4][kk2][mblk2][lane32] uint4 (1024)
__device__ __align__(16) uint4  g_Wf[(size_t)Ld * NCTA * 32 * 1024];  // 128 MB
__device__ __align__(16) __half g_WoutH[OUTD][Hd];
__device__ float  g_bias[Ld][NCTA][64];
__device__ float  g_bout[OUTD];
__device__ __align__(16) __half g_H0[2][Hd][Bd];      // layer-0 h ping-pong [k][b]
__device__ __align__(16) __half g_H1all[Td][Hd][Bd];  // layer-1 h, all steps
__device__ __align__(16) __half g_H1init[Hd][Bd];
__device__ __align__(16) __half g_Xzero[Hd][Bd];
__device__ unsigned g_count;

// ------------------------------ PTX helpers --------------------------------
__device__ __forceinline__ unsigned sptr(const void* p) {
    return (unsigned)__cvta_generic_to_shared(p);
}
__device__ __forceinline__ void cpa16(unsigned dst, const void* src) {
    asm volatile("cp.async.cg.shared.global [%0], [%1], 16;\n" :: "r"(dst), "l"(src));
}
__device__ __forceinline__ void cpa_commit() {
    asm volatile("cp.async.commit_group;\n" ::: "memory");
}
template <int N>
__device__ __forceinline__ void cpa_wait() {
    asm volatile("cp.async.wait_group %0;\n" :: "n"(N) : "memory");
}
__device__ __forceinline__ void ldsm4(unsigned& r0, unsigned& r1, unsigned& r2,
                                      unsigned& r3, unsigned a) {
    asm volatile("ldmatrix.sync.aligned.m8n8.x4.shared.b16 {%0,%1,%2,%3},[%4];\n"
                 : "=r"(r0), "=r"(r1), "=r"(r2), "=r"(r3) : "r"(a));
}
__device__ __forceinline__ void ldsm4t(unsigned& r0, unsigned& r1, unsigned& r2,
                                       unsigned& r3, unsigned a) {
    asm volatile("ldmatrix.sync.aligned.m8n8.x4.trans.shared.b16 {%0,%1,%2,%3},[%4];\n"
                 : "=r"(r0), "=r"(r1), "=r"(r2), "=r"(r3) : "r"(a));
}
__device__ __forceinline__ void mma16816(float* d, unsigned a0, unsigned a1,
                                         unsigned a2, unsigned a3,
                                         unsigned b0, unsigned b1) {
    asm volatile(
        "mma.sync.aligned.m16n8k16.row.col.f32.f16.f16.f32 "
        "{%0,%1,%2,%3},{%4,%5,%6,%7},{%8,%9},{%0,%1,%2,%3};\n"
        : "+f"(d[0]), "+f"(d[1]), "+f"(d[2]), "+f"(d[3])
        : "r"(a0), "r"(a1), "r"(a2), "r"(a3), "r"(b0), "r"(b1));
}
__device__ __forceinline__ float sgm(float x) { return 1.f / (1.f + __expf(-x)); }

__device__ __forceinline__ void gridbar(unsigned& target) {
    __syncthreads();
    if (threadIdx.x == 0) {
        __threadfence();
        target += (unsigned)gridDim.x;
        atomicAdd(&g_count, 1u);
        unsigned v;
        for (;;) {
            asm volatile("ld.acquire.gpu.global.u32 %0, [%1];" : "=r"(v) : "l"(&g_count));
            if (v >= target) break;
            __nanosleep(32);
        }
    }
    __syncthreads();
}

// ------------------------------ prep kernels -------------------------------
// Warp wid: wm = wid>>3 (32-row half), wn = (wid>>2)&1 (n32), wk = wid&3 (k32).
__global__ void pack_w_kernel(const float* __restrict__ Wih,
                              const float* __restrict__ Whh) {
    int idx = blockIdx.x * blockDim.x + threadIdx.x;   // 8,388,608
    int lane = idx & 31;
    int mblk = (idx >> 5) & 1;
    int kk   = (idx >> 6) & 1;
    int wk   = (idx >> 7) & 3;
    int wm   = (idx >> 9) & 1;
    int kc   = (idx >> 10) & 31;
    int ct   = (idx >> 15) & 127;
    int l    = idx >> 22;
    if (l >= Ld) return;
    int r0 = wm * 32 + mblk * 16 + (lane >> 2);
    int k0 = kc * 128 + wk * 32 + kk * 16 + (lane & 3) * 2;

    auto ld2 = [&](int r, int k) -> float2 {
        int grow = (r >> 4) * 2048 + ct * 16 + (r & 15);
        const float* s = (k < 2048)
            ? (Wih + ((size_t)(l * 8192 + grow)) * 2048 + k)
            : (Whh + ((size_t)(l * 8192 + grow)) * 2048 + (k - 2048));
        return *reinterpret_cast<const float2*>(s);
    };
    float2 v0 = ld2(r0,     k0);
    float2 v1 = ld2(r0 + 8, k0);
    float2 v2 = ld2(r0,     k0 + 8);
    float2 v3 = ld2(r0 + 8, k0 + 8);

    __half2 h0 = __floats2half2_rn(v0.x, v0.y);
    __half2 h1 = __floats2half2_rn(v1.x, v1.y);
    __half2 h2 = __floats2half2_rn(v2.x, v2.y);
    __half2 h3 = __floats2half2_rn(v3.x, v3.y);
    uint4 o;
    o.x = *reinterpret_cast<unsigned*>(&h0);
    o.y = *reinterpret_cast<unsigned*>(&h1);
    o.z = *reinterpret_cast<unsigned*>(&h2);
    o.w = *reinterpret_cast<unsigned*>(&h3);

    size_t off = ((((size_t)(l * NCTA + ct) * 32 + kc)) * 1024)
               + (size_t)((wm * 4 + wk) * 128 + kk * 64 + mblk * 32 + lane);
    g_Wf[off] = o;
}

__global__ void pack_wout_kernel(const float* __restrict__ Wout) {
    int idx = blockIdx.x * blockDim.x + threadIdx.x;
    int k0 = (idx & 511) * 4;
    int row = idx >> 9;
    if (row >= OUTD) return;
    float4 v = *reinterpret_cast<const float4*>(Wout + (size_t)row * Hd + k0);
    __half2* dst = reinterpret_cast<__half2*>(&g_WoutH[row][k0]);
    dst[0] = __floats2half2_rn(v.x, v.y);
    dst[1] = __floats2half2_rn(v.z, v.w);
}

__global__ void pack_misc_kernel(const float* __restrict__ h0,
                                 const float* __restrict__ bih,
                                 const float* __restrict__ bhh,
                                 const float* __restrict__ bout) {
    int i = blockIdx.x * blockDim.x + threadIdx.x;   // 131072
    if (i == 0) g_count = 0u;
    if (i < OUTD) g_bout[i] = bout[i];
    if (i < Ld * NCTA * 64) {
        int r = i & 63, ct = (i >> 6) & 127, l = i >> 13;
        int row = (r >> 4) * 2048 + ct * 16 + (r & 15);
        g_bias[l][ct][r] = bih[l * 8192 + row] + bhh[l * 8192 + row];
    }
    if (i < Hd * Bd) {
        int b = i & 63, j = i >> 6;
        g_H0[1][j][b]  = __float2half_rn(h0[(size_t)b * Hd + j]);
        g_H1init[j][b] = __float2half_rn(h0[(size_t)(Bd + b) * Hd + j]);
        g_Xzero[j][b]  = __float2half_rn(0.f);
    }
}

// ----------------------- chunk loader (W + B via cp.async) ------------------
__device__ __forceinline__ void issue_chunk(unsigned su, int stage,
                                            const uint4* __restrict__ Wc,
                                            const __half* __restrict__ Bs,
                                            int tid) {
    unsigned wb = su + stage * STB;
    unsigned bb = wb + WB;
#pragma unroll
    for (int it = 0; it < 4; it++) {
        int u = tid + it * THRM;          // 0..2047
        if (u < 1024) {                   // W: 1024 uint4, contiguous
            cpa16(wb + (unsigned)(u * 16), Wc + u);
        } else {                          // B: 128 rows x 128 B into APAD rows
            int v = u - 1024;
            int row = v >> 3, col8 = (v & 7) * 8;
            cpa16(bb + (unsigned)((row * APAD + col8) * 2),
                  Bs + (size_t)row * Bd + col8);
        }
    }
}

// --------------------------- gates GEMM (16 warps) ---------------------------
// D[64][64] = W[64][4096] x act[4096][64]. Warp grid wm2 x wn2 x wk4.
// Paired-chunk pipeline: one barrier per 2 chunks, 6-stage ring, 4 groups deep.
__device__ __forceinline__ void gemm_gates(const uint4* __restrict__ Wf,
                                           const __half* __restrict__ Xg,
                                           const __half* __restrict__ Hg,
                                           char* smem,
                                           const float* __restrict__ bias,
                                           int tid, int lane, int wid) {
    const int wm = wid >> 3, wn = (wid >> 2) & 1, wk = wid & 3;
    const unsigned su = sptr(smem);
    float acc[2][4][4];
#pragma unroll
    for (int a = 0; a < 2; a++)
#pragma unroll
        for (int b = 0; b < 4; b++)
#pragma unroll
            for (int c = 0; c < 4; c++) acc[a][b][c] = 0.f;

    // prologue: chunks 0..3 into stages 0..3
#pragma unroll
    for (int pc = 0; pc < 4; pc++) {
        const __half* Bs = (pc < 16) ? (Xg + (size_t)pc * KC * Bd)
                                     : (Hg + (size_t)(pc - 16) * KC * Bd);
        issue_chunk(su, pc, Wf + pc * 1024, Bs, tid);
        cpa_commit();
    }

#pragma unroll 1
    for (int p = 0; p < 32; p += 2) {
        cpa_wait<2>();     // chunks p, p+1 landed (p+2, p+3 still in flight)
        __syncthreads();   // stages (p+4)%6, (p+5)%6 fully consumed 2 iters ago

        // issue chunks p+4, p+5
#pragma unroll
        for (int q = 0; q < 2; q++) {
            int ni = p + 4 + q;
            if (ni < 32) {
                const __half* Bs = (ni < 16) ? (Xg + (size_t)ni * KC * Bd)
                                             : (Hg + (size_t)(ni - 16) * KC * Bd);
                issue_chunk(su, ni % ST, Wf + ni * 1024, Bs, tid);
            }
            cpa_commit();
        }

        // compute chunks p, p+1
#pragma unroll
        for (int q = 0; q < 2; q++) {
            int kc = p + q;
            int st = kc % ST;
            const char* stg = smem + st * STB;
            const char* wst = stg + (wm * 4 + wk) * 2048;
            uint4 w[4];
#pragma unroll
            for (int kk = 0; kk < 2; kk++)
#pragma unroll
                for (int mb = 0; mb < 2; mb++)
                    w[kk * 2 + mb] = *reinterpret_cast<const uint4*>(
                        wst + kk * 1024 + mb * 512 + lane * 16);

            unsigned bB = su + st * STB + WB
                        + (unsigned)(((wk * 32 + (lane & 15)) * APAD
                                      + wn * 32 + (lane >> 4) * 8) * 2);
#pragma unroll
            for (int kk = 0; kk < 2; kk++) {
                unsigned bk = bB + (unsigned)(kk * 16 * APAD * 2);
#pragma unroll
                for (int n2 = 0; n2 < 2; n2++) {
                    unsigned b0, b1, b2, b3;
                    ldsm4t(b0, b1, b2, b3, bk + (unsigned)(n2 * 32));
                    uint4 A0 = w[kk * 2 + 0], A1 = w[kk * 2 + 1];
                    mma16816(acc[0][n2 * 2 + 0], A0.x, A0.y, A0.z, A0.w, b0, b1);
                    mma16816(acc[0][n2 * 2 + 1], A0.x, A0.y, A0.z, A0.w, b2, b3);
                    mma16816(acc[1][n2 * 2 + 0], A1.x, A1.y, A1.z, A1.w, b0, b1);
                    mma16816(acc[1][n2 * 2 + 1], A1.x, A1.y, A1.z, A1.w, b2, b3);
                }
            }
        }
    }
    __syncthreads();   // all stage data dead; sP/sG aliases become safe

    // 4-way k reduction (sP/sG alias ring stages 0-1)
    float* sP = reinterpret_cast<float*>(smem + SP_OFF);
    float* sG = reinterpret_cast<float*>(smem + SG_OFF);
    const int gid = lane >> 2, tig = lane & 3;
    if (wk > 0) {
        float* P = sP + (wk - 1) * 64 * PPAD;
#pragma unroll
        for (int mb = 0; mb < 2; mb++) {
            int r = wm * 32 + mb * 16 + gid;
#pragma unroll
            for (int nb = 0; nb < 4; nb++) {
                int c = wn * 32 + nb * 8 + tig * 2;
                *reinterpret_cast<float2*>(&P[r * PPAD + c]) =
                    make_float2(acc[mb][nb][0], acc[mb][nb][1]);
                *reinterpret_cast<float2*>(&P[(r + 8) * PPAD + c]) =
                    make_float2(acc[mb][nb][2], acc[mb][nb][3]);
            }
        }
    }
    __syncthreads();
    if (wk == 0) {
#pragma unroll
        for (int mb = 0; mb < 2; mb++) {
            int r = wm * 32 + mb * 16 + gid;
            float bv0 = bias[r], bv1 = bias[r + 8];
#pragma unroll
            for (int nb = 0; nb < 4; nb++) {
                int c = wn * 32 + nb * 8 + tig * 2;
                float s00 = acc[mb][nb][0] + bv0, s01 = acc[mb][nb][1] + bv0;
                float s10 = acc[mb][nb][2] + bv1, s11 = acc[mb][nb][3] + bv1;
#pragma unroll
                for (int pp = 0; pp < 3; pp++) {
                    const float* P = sP + pp * 64 * PPAD;
                    float2 u0 = *reinterpret_cast<const float2*>(&P[r * PPAD + c]);
                    float2 u1 = *reinterpret_cast<const float2*>(&P[(r + 8) * PPAD + c]);
                    s00 += u0.x; s01 += u0.y; s10 += u1.x; s11 += u1.y;
                }
                sG[r * GPAD + c]           = s00;
                sG[r * GPAD + c + 1]       = s01;
                sG[(r + 8) * GPAD + c]     = s10;
                sG[(r + 8) * GPAD + c + 1] = s11;
            }
        }
    }
    __syncthreads();
}

__device__ __forceinline__ void pointwise(const float* sG, float* cst,
                                          __half* Hout, int ct, int tid) {
#pragma unroll
    for (int e = 0; e < 2; e++) {
        int idx = tid + e * THRM;        // 16 hidden x 64 batch
        int b = idx & 63, jj = idx >> 6;
        float gi = sG[jj * GPAD + b];
        float gf = sG[(16 + jj) * GPAD + b];
        float gg = sG[(32 + jj) * GPAD + b];
        float go = sG[(48 + jj) * GPAD + b];
        float c = sgm(gf) * cst[e] + sgm(gi) * tanhf(gg);
        cst[e] = c;
        Hout[(ct * 16 + jj) * Bd + b] = __float2half_rn(sgm(go) * tanhf(c));
    }
}

// ------------------------------- main kernel -------------------------------
__global__ void __launch_bounds__(THRM, 1)
lstm_main(const float* __restrict__ c0) {
    extern __shared__ char smem[];
    float* sG = reinterpret_cast<float*>(smem + SG_OFF);

    const int tid = threadIdx.x, lane = tid & 31, wid = tid >> 5;
    const int ct = blockIdx.x;

    float cst0[2], cst1[2];
#pragma unroll
    for (int e = 0; e < 2; e++) {
        int idx = tid + e * THRM;
        int b = idx & 63, j = ct * 16 + (idx >> 6);
        cst0[e] = c0[(size_t)b * Hd + j];
        cst1[e] = c0[(size_t)(Bd + b) * Hd + j];
    }

    const uint4* W0 = g_Wf + ((size_t)0 * NCTA + ct) * 32768;
    const uint4* W1 = g_Wf + ((size_t)1 * NCTA + ct) * 32768;
    const float* bias0 = &g_bias[0][ct][0];
    const float* bias1 = &g_bias[1][ct][0];
    unsigned target = 0;

    for (int t = 0; t < Td; t++) {
        const int p = t & 1;
        const __half* X0  = (t == 0) ? &g_Xzero[0][0] : &g_H1all[t - 1][0][0];
        const __half* Hp0 = &g_H0[p ^ 1][0][0];
        gemm_gates(W0, X0, Hp0, smem, bias0, tid, lane, wid);
        pointwise(sG, cst0, &g_H0[p][0][0], ct, tid);
        gridbar(target);

        const __half* X1  = &g_H0[p][0][0];
        const __half* Hp1 = (t == 0) ? &g_H1init[0][0] : &g_H1all[t - 1][0][0];
        gemm_gates(W1, X1, Hp1, smem, bias1, tid, lane, wid);
        pointwise(sG, cst1, &g_H1all[t][0][0], ct, tid);
        gridbar(target);
    }
}

// -------------------- proj GEMM (off critical path) -------------------------
template <int KTOT>
__device__ __forceinline__ void gemm64_old(const __half* __restrict__ Wg,
                                           const __half* __restrict__ Xg,
                                           __half* sW, __half* sA, float* sG,
                                           const float* __restrict__ bias,
                                           int tid, int lane, int wid) {
    constexpr int NCHUNK = KTOT / KC;
    float acc[4][4];
#pragma unroll
    for (int i = 0; i < 4; i++)
#pragma unroll
        for (int j = 0; j < 4; j++) acc[i][j] = 0.f;
    const int wm = wid >> 1, wn = wid & 1;

    uint4 wr[4], ar[4];
#pragma unroll
    for (int i = 0; i < 4; i++) {
        int s = tid + i * THRP;
        wr[i] = *reinterpret_cast<const uint4*>(Wg + (size_t)(s >> 4) * KTOT + (s & 15) * 8);
    }
#pragma unroll
    for (int i = 0; i < 4; i++) {
        int s = tid + i * THRP;
        ar[i] = *reinterpret_cast<const uint4*>(Xg + (size_t)(s >> 3) * Bd + (s & 7) * 8);
    }

#pragma unroll 1
    for (int kc = 0; kc < NCHUNK; kc++) {
        __half* sWc = sW + (kc & 1) * 64 * WPAD;
        __half* sAc = sA + (kc & 1) * KC * APAD;
#pragma unroll
        for (int i = 0; i < 4; i++) {
            int s = tid + i * THRP;
            *reinterpret_cast<uint4*>(sWc + (s >> 4) * WPAD + (s & 15) * 8) = wr[i];
        }
#pragma unroll
        for (int i = 0; i < 4; i++) {
            int s = tid + i * THRP;
            *reinterpret_cast<uint4*>(sAc + (s >> 3) * APAD + (s & 7) * 8) = ar[i];
        }
        __syncthreads();

        if (kc + 1 < NCHUNK) {
            int k0 = (kc + 1) * KC;
#pragma unroll
            for (int i = 0; i < 4; i++) {
                int s = tid + i * THRP;
                wr[i] = *reinterpret_cast<const uint4*>(
                    Wg + (size_t)(s >> 4) * KTOT + k0 + (s & 15) * 8);
            }
#pragma unroll
            for (int i = 0; i < 4; i++) {
                int s = tid + i * THRP;
                ar[i] = *reinterpret_cast<const uint4*>(
                    Xg + (size_t)(k0 + (s >> 3)) * Bd + (s & 7) * 8);
            }
        }

        unsigned aBase = sptr(sWc + (wm * 16 + (lane & 15)) * WPAD + (lane >> 4) * 8);
        unsigned bBase = sptr(sAc + (lane & 15) * APAD + wn * 32 + (lane >> 4) * 8);
#pragma unroll
        for (int kk = 0; kk < KC / 16; kk++) {
            unsigned a0, a1, a2, a3;
            ldsm4(a0, a1, a2, a3, aBase + kk * 32);
#pragma unroll
            for (int nb2 = 0; nb2 < 2; nb2++) {
                unsigned b0, b1, b2, b3;
                ldsm4t(b0, b1, b2, b3,
                       bBase + (unsigned)((kk * 16 * APAD + nb2 * 16) * 2));
                mma16816(acc[nb2 * 2 + 0], a0, a1, a2, a3, b0, b1);
                mma16816(acc[nb2 * 2 + 1], a0, a1, a2, a3, b2, b3);
            }
        }
        __syncthreads();
    }

    {
        int rbase = wm * 16 + (lane >> 2);
        float bs0 = bias[rbase], bs1 = bias[rbase + 8];
#pragma unroll
        for (int nb = 0; nb < 4; nb++) {
            int cb = wn * 32 + nb * 8 + (lane & 3) * 2;
            sG[rbase * GPAD + cb]           = acc[nb][0] + bs0;
            sG[rbase * GPAD + cb + 1]       = acc[nb][1] + bs0;
            sG[(rbase + 8) * GPAD + cb]     = acc[nb][2] + bs1;
            sG[(rbase + 8) * GPAD + cb + 1] = acc[nb][3] + bs1;
        }
    }
    __syncthreads();
}

__global__ void __launch_bounds__(THRP)
proj_kernel(float* __restrict__ out) {
    extern __shared__ char smem[];
    __half* sW = reinterpret_cast<__half*>(smem);
    __half* sA = reinterpret_cast<__half*>(smem + SMEM_W_OLD);
    float*  sG = reinterpret_cast<float*>(smem + SMEM_W_OLD + SMEM_A_OLD);

    const int tid = threadIdx.x, lane = tid & 31, wid = tid >> 5;
    const int bx = blockIdx.x;
    const int t  = blockIdx.y;

    gemm64_old<Hd>(&g_WoutH[bx * 64][0], &g_H1all[t][0][0],
                   sW, sA, sG, &g_bout[bx * 64], tid, lane, wid);

#pragma unroll
    for (int e = 0; e < 16; e++) {
        int idx = tid + e * THRP;
        int b = idx >> 6, oo = idx & 63;
        out[((size_t)(t * Bd + b)) * OUTD + bx * 64 + oo] = sG[oo * GPAD + b];
    }
}

// ------------------------------- entry point -------------------------------
extern "C" void kernel_launch(void* const* d_in, const int* in_sizes, int n_in,
                              void* d_out, int out_size) {
    const float* h0   = (const float*)d_in[0];
    const float* c0   = (const float*)d_in[1];
    const float* Wih  = (const float*)d_in[2];
    const float* Whh  = (const float*)d_in[3];
    const float* bih  = (const float*)d_in[4];
    const float* bhh  = (const float*)d_in[5];
    const float* Wout = (const float*)d_in[6];
    const float* bout = (const float*)d_in[7];
    float* out = (float*)d_out;

    cudaFuncSetAttribute(lstm_main, cudaFuncAttributeMaxDynamicSharedMemorySize, SMEM_MAIN);
    cudaFuncSetAttribute(proj_kernel, cudaFuncAttributeMaxDynamicSharedMemorySize, SMEM_PROJ);

    pack_w_kernel<<<32768, 256>>>(Wih, Whh);
    pack_wout_kernel<<<2048, 256>>>(Wout);
    pack_misc_kernel<<<512, 256>>>(h0, bih, bhh, bout);  // also resets g_count
    lstm_main<<<NCTA, THRM, SMEM_MAIN>>>(c0);
    proj_kernel<<<dim3(16, Td), THRP, SMEM_PROJ>>>(out);
}

// round 14
// speedup vs baseline: 1.2785x; 1.2785x over previous
#include <cuda_runtime.h>
#include <cuda_fp16.h>
#include <cstdint>

#define Ld    2
#define Hd    2048
#define OUTD  1024
#define Bd    64
#define Td    256
#define NCTA  128
#define THRM  512   // 16 warps
#define THRP  256
#define KC    128

#define APAD  72
#define GPAD  68
#define PPAD  68
#define WPAD  136   // proj path only

#define PANB  262144        // bytes per activation panel (16 chunks x 16384)
#define SST   32768         // stage bytes: W 16K + B 16K
#define MB_OFF 131072       // 4 mbarriers
#define SP_OFF 131328
#define SG_OFF (SP_OFF + 3 * 64 * PPAD * 4)     // 183552
#define SMEM_MAIN (SG_OFF + 64 * GPAD * 4)      // 200960

// proj smem
#define SMEM_A_OLD (2 * KC * APAD * 2)
#define SMEM_W_OLD (2 * 64 * WPAD * 2)
#define SMEM_G_OLD (64 * GPAD * 4)
#define SMEM_PROJ  (SMEM_W_OLD + SMEM_A_OLD + SMEM_G_OLD)

// ----------------------------- device globals ------------------------------
// W fragments per (l,ct,chunk): [wm2*wk4][kk2][mblk2][lane32] uint4 (16KB)
__device__ __align__(16)  uint4 g_Wf[(size_t)Ld * NCTA * 32 * 1024];  // 128 MB
__device__ __align__(16)  __half g_WoutH[OUTD][Hd];
__device__ float g_bias[Ld][NCTA][64];
__device__ float g_bout[OUTD];
// activation panels: chunked swizzled [chunk16][k128][b64], 16KB/chunk
__device__ __align__(128) char g_H0[2][PANB];
__device__ __align__(128) char g_H1all[Td][PANB];   // 64 MB
__device__ __align__(128) char g_H1init[PANB];
__device__ __align__(128) char g_Xz[PANB];
__device__ unsigned g_count;

// ------------------------------ PTX helpers --------------------------------
__device__ __forceinline__ unsigned sptr(const void* p) {
    return (unsigned)__cvta_generic_to_shared(p);
}
__device__ __forceinline__ void mbar_init(unsigned a, unsigned c) {
    asm volatile("mbarrier.init.shared.b64 [%0], %1;" :: "r"(a), "r"(c) : "memory");
}
__device__ __forceinline__ void mbar_expect(unsigned a, unsigned bytes) {
    asm volatile("mbarrier.arrive.expect_tx.shared.b64 _, [%0], %1;"
                 :: "r"(a), "r"(bytes) : "memory");
}
__device__ __forceinline__ void bulk_g2s(unsigned dst, const void* src,
                                         unsigned bytes, unsigned mb) {
    asm volatile(
        "cp.async.bulk.shared::cta.global.mbarrier::complete_tx::bytes "
        "[%0], [%1], %2, [%3];"
        :: "r"(dst), "l"(src), "r"(bytes), "r"(mb) : "memory");
}
__device__ __forceinline__ void mbar_wait(unsigned a, unsigned par) {
    asm volatile(
        "{\n\t.reg .pred P;\n\tWL_%=:\n\t"
        "mbarrier.try_wait.parity.acquire.cta.shared::cta.b64 P, [%0], %1, 0x989680;\n\t"
        "@!P bra WL_%=;\n\t}" :: "r"(a), "r"(par) : "memory");
}
__device__ __forceinline__ void ldsm4(unsigned& r0, unsigned& r1, unsigned& r2,
                                      unsigned& r3, unsigned a) {
    asm volatile("ldmatrix.sync.aligned.m8n8.x4.shared.b16 {%0,%1,%2,%3},[%4];\n"
                 : "=r"(r0), "=r"(r1), "=r"(r2), "=r"(r3) : "r"(a));
}
__device__ __forceinline__ void ldsm4t(unsigned& r0, unsigned& r1, unsigned& r2,
                                       unsigned& r3, unsigned a) {
    asm volatile("ldmatrix.sync.aligned.m8n8.x4.trans.shared.b16 {%0,%1,%2,%3},[%4];\n"
                 : "=r"(r0), "=r"(r1), "=r"(r2), "=r"(r3) : "r"(a));
}
__device__ __forceinline__ void mma16816(float* d, unsigned a0, unsigned a1,
                                         unsigned a2, unsigned a3,
                                         unsigned b0, unsigned b1) {
    asm volatile(
        "mma.sync.aligned.m16n8k16.row.col.f32.f16.f16.f32 "
        "{%0,%1,%2,%3},{%4,%5,%6,%7},{%8,%9},{%0,%1,%2,%3};\n"
        : "+f"(d[0]), "+f"(d[1]), "+f"(d[2]), "+f"(d[3])
        : "r"(a0), "r"(a1), "r"(a2), "r"(a3), "r"(b0), "r"(b1));
}
// legacy cp.async (proj only)
__device__ __forceinline__ float sgm(float x) { return 1.f / (1.f + __expf(-x)); }

__device__ __forceinline__ void gridbar(unsigned& target) {
    __syncthreads();
    if (threadIdx.x == 0) {
        __threadfence();
        target += (unsigned)gridDim.x;
        atomicAdd(&g_count, 1u);
        unsigned v;
        for (;;) {
            asm volatile("ld.acquire.gpu.global.u32 %0, [%1];" : "=r"(v) : "l"(&g_count));
            if (v >= target) break;
            __nanosleep(32);
        }
    }
    __syncthreads();
}

// swizzled read of one uint4 from a chunked activation panel (proj path)
__device__ __forceinline__ uint4 ld_act(const char* P, int row, int col8) {
    unsigned off = (unsigned)((row & 127) * 128 + col8 * 2);
    off ^= (off >> 3) & 0x70;
    return *reinterpret_cast<const uint4*>(P + (size_t)(row >> 7) * 16384 + off);
}

// ------------------------------ prep kernels -------------------------------
// W fragment pack (same layout as R12): warp = wm*4+wk; [kk2][mblk2][lane32].
__global__ void pack_w_kernel(const float* __restrict__ Wih,
                              const float* __restrict__ Whh) {
    int idx = blockIdx.x * blockDim.x + threadIdx.x;   // 8,388,608
    int lane = idx & 31;
    int mblk = (idx >> 5) & 1;
    int kk   = (idx >> 6) & 1;
    int wk   = (idx >> 7) & 3;
    int wm   = (idx >> 9) & 1;
    int kc   = (idx >> 10) & 31;
    int ct   = (idx >> 15) & 127;
    int l    = idx >> 22;
    if (l >= Ld) return;
    int r0 = wm * 32 + mblk * 16 + (lane >> 2);
    int k0 = kc * 128 + wk * 32 + kk * 16 + (lane & 3) * 2;

    auto ld2 = [&](int r, int k) -> float2 {
        int grow = (r >> 4) * 2048 + ct * 16 + (r & 15);
        const float* s = (k < 2048)
            ? (Wih + ((size_t)(l * 8192 + grow)) * 2048 + k)
            : (Whh + ((size_t)(l * 8192 + grow)) * 2048 + (k - 2048));
        return *reinterpret_cast<const float2*>(s);
    };
    float2 v0 = ld2(r0,     k0);
    float2 v1 = ld2(r0 + 8, k0);
    float2 v2 = ld2(r0,     k0 + 8);
    float2 v3 = ld2(r0 + 8, k0 + 8);

    __half2 h0 = __floats2half2_rn(v0.x, v0.y);
    __half2 h1 = __floats2half2_rn(v1.x, v1.y);
    __half2 h2 = __floats2half2_rn(v2.x, v2.y);
    __half2 h3 = __floats2half2_rn(v3.x, v3.y);
    uint4 o;
    o.x = *reinterpret_cast<unsigned*>(&h0);
    o.y = *reinterpret_cast<unsigned*>(&h1);
    o.z = *reinterpret_cast<unsigned*>(&h2);
    o.w = *reinterpret_cast<unsigned*>(&h3);

    size_t off = ((((size_t)(l * NCTA + ct) * 32 + kc)) * 1024)
               + (size_t)((wm * 4 + wk) * 128 + kk * 64 + mblk * 32 + lane);
    g_Wf[off] = o;
}

__global__ void pack_wout_kernel(const float* __restrict__ Wout) {
    int idx = blockIdx.x * blockDim.x + threadIdx.x;
    int k0 = (idx & 511) * 4;
    int row = idx >> 9;
    if (row >= OUTD) return;
    float4 v = *reinterpret_cast<const float4*>(Wout + (size_t)row * Hd + k0);
    __half2* dst = reinterpret_cast<__half2*>(&g_WoutH[row][k0]);
    dst[0] = __floats2half2_rn(v.x, v.y);
    dst[1] = __floats2half2_rn(v.z, v.w);
}

__global__ void pack_misc_kernel(const float* __restrict__ h0,
                                 const float* __restrict__ bih,
                                 const float* __restrict__ bhh,
                                 const float* __restrict__ bout) {
    int i = blockIdx.x * blockDim.x + threadIdx.x;   // 131072
    if (i == 0) g_count = 0u;
    if (i < OUTD) g_bout[i] = bout[i];
    if (i < Ld * NCTA * 64) {
        int r = i & 63, ct = (i >> 6) & 127, l = i >> 13;
        int row = (r >> 4) * 2048 + ct * 16 + (r & 15);
        g_bias[l][ct][r] = bih[l * 8192 + row] + bhh[l * 8192 + row];
    }
    {   // swizzled panel writes (bijective over the panel)
        int j = i >> 6, b = i & 63;
        unsigned off = (unsigned)((j & 127) * 128 + b * 2);
        off ^= (off >> 3) & 0x70;
        size_t pos = (size_t)(j >> 7) * 16384 + off;
        *reinterpret_cast<__half*>(g_H0[1] + pos) =
            __float2half_rn(h0[(size_t)b * Hd + j]);
        *reinterpret_cast<__half*>(g_H1init + pos) =
            __float2half_rn(h0[(size_t)(Bd + b) * Hd + j]);
        *reinterpret_cast<__half*>(g_Xz + pos) = __float2half_rn(0.f);
    }
}

// ----------------------- bulk chunk issue (1 thread) ------------------------
__device__ __forceinline__ void issue_chunk(unsigned su, int gi, int c,
                                            const uint4* __restrict__ Wf,
                                            const char* __restrict__ Xg,
                                            const char* __restrict__ Hg) {
    unsigned mb  = su + MB_OFF + (unsigned)(gi & 3) * 8;
    unsigned dst = su + (unsigned)(gi & 3) * SST;
    const char* Bs = (c < 16) ? (Xg + (size_t)c * 16384)
                              : (Hg + (size_t)(c - 16) * 16384);
    mbar_expect(mb, 32768u);
    bulk_g2s(dst, Wf + (size_t)c * 1024, 16384u, mb);
    bulk_g2s(dst + 16384u, Bs, 16384u, mb);
}

// --------------------------- gates GEMM (16 warps) ---------------------------
// D[64][64] = W[64][4096] x act[4096][64]. Warp grid wm2 x wn2 x wk4.
__device__ __forceinline__ void gemm_gates(const uint4* __restrict__ Wf,
                                           const char* __restrict__ Xg,
                                           const char* __restrict__ Hg,
                                           char* smem,
                                           const float* __restrict__ bias,
                                           int tid, int lane, int wid, int gcb) {
    const int wm = wid >> 3, wn = (wid >> 2) & 1, wk = wid & 3;
    const unsigned su = sptr(smem);
    float acc[2][4][4];
#pragma unroll
    for (int a = 0; a < 2; a++)
#pragma unroll
        for (int b = 0; b < 4; b++)
#pragma unroll
            for (int c = 0; c < 4; c++) acc[a][b][c] = 0.f;

    if (tid == 0) {
#pragma unroll
        for (int pc = 0; pc < 3; pc++) issue_chunk(su, gcb + pc, pc, Wf, Xg, Hg);
    }

#pragma unroll 1
    for (int kc = 0; kc < 32; kc++) {
        const int gi = gcb + kc;
        mbar_wait(su + MB_OFF + (unsigned)(gi & 3) * 8, (unsigned)(gi >> 2) & 1u);
        __syncthreads();   // stage (gi+3)&3 = (gi-1)&3 consumed by all warps
        if (tid == 0 && kc + 3 < 32)
            issue_chunk(su, gi + 3, kc + 3, Wf, Xg, Hg);

        const char* stg = smem + (size_t)(gi & 3) * SST;
        const char* wst = stg + (wm * 4 + wk) * 2048;
        uint4 w[4];
#pragma unroll
        for (int kk = 0; kk < 2; kk++)
#pragma unroll
            for (int mb = 0; mb < 2; mb++)
                w[kk * 2 + mb] = *reinterpret_cast<const uint4*>(
                    wst + kk * 1024 + mb * 512 + lane * 16);

        const unsigned bbu = su + (unsigned)(gi & 3) * SST + 16384u;
#pragma unroll
        for (int kk = 0; kk < 2; kk++) {
            int krow = wk * 32 + kk * 16 + (lane & 15);
#pragma unroll
            for (int n2 = 0; n2 < 2; n2++) {
                unsigned off = (unsigned)(krow * 128
                             + wn * 64 + (lane >> 4) * 16 + n2 * 32);
                off ^= (off >> 3) & 0x70;
                unsigned b0, b1, b2, b3;
                ldsm4t(b0, b1, b2, b3, bbu + off);
                uint4 A0 = w[kk * 2 + 0], A1 = w[kk * 2 + 1];
                mma16816(acc[0][n2 * 2 + 0], A0.x, A0.y, A0.z, A0.w, b0, b1);
                mma16816(acc[0][n2 * 2 + 1], A0.x, A0.y, A0.z, A0.w, b2, b3);
                mma16816(acc[1][n2 * 2 + 0], A1.x, A1.y, A1.z, A1.w, b0, b1);
                mma16816(acc[1][n2 * 2 + 1], A1.x, A1.y, A1.z, A1.w, b2, b3);
            }
        }
    }
    __syncthreads();

    // 4-way k reduction
    float* sP = reinterpret_cast<float*>(smem + SP_OFF);
    float* sG = reinterpret_cast<float*>(smem + SG_OFF);
    const int gid = lane >> 2, tig = lane & 3;
    if (wk > 0) {
        float* P = sP + (wk - 1) * 64 * PPAD;
#pragma unroll
        for (int mb = 0; mb < 2; mb++) {
            int r = wm * 32 + mb * 16 + gid;
#pragma unroll
            for (int nb = 0; nb < 4; nb++) {
                int c = wn * 32 + nb * 8 + tig * 2;
                *reinterpret_cast<float2*>(&P[r * PPAD + c]) =
                    make_float2(acc[mb][nb][0], acc[mb][nb][1]);
                *reinterpret_cast<float2*>(&P[(r + 8) * PPAD + c]) =
                    make_float2(acc[mb][nb][2], acc[mb][nb][3]);
            }
        }
    }
    __syncthreads();
    if (wk == 0) {
#pragma unroll
        for (int mb = 0; mb < 2; mb++) {
            int r = wm * 32 + mb * 16 + gid;
            float bv0 = bias[r], bv1 = bias[r + 8];
#pragma unroll
            for (int nb = 0; nb < 4; nb++) {
                int c = wn * 32 + nb * 8 + tig * 2;
                float s00 = acc[mb][nb][0] + bv0, s01 = acc[mb][nb][1] + bv0;
                float s10 = acc[mb][nb][2] + bv1, s11 = acc[mb][nb][3] + bv1;
#pragma unroll
                for (int pp = 0; pp < 3; pp++) {
                    const float* P = sP + pp * 64 * PPAD;
                    float2 u0 = *reinterpret_cast<const float2*>(&P[r * PPAD + c]);
                    float2 u1 = *reinterpret_cast<const float2*>(&P[(r + 8) * PPAD + c]);
                    s00 += u0.x; s01 += u0.y; s10 += u1.x; s11 += u1.y;
                }
                sG[r * GPAD + c]           = s00;
                sG[r * GPAD + c + 1]       = s01;
                sG[(r + 8) * GPAD + c]     = s10;
                sG[(r + 8) * GPAD + c + 1] = s11;
            }
        }
    }
    __syncthreads();
}

__device__ __forceinline__ void pointwise(const float* sG, float* cst,
                                          char* panel, int ct, int tid) {
#pragma unroll
    for (int e = 0; e < 2; e++) {
        int idx = tid + e * THRM;        // 16 hidden x 64 batch
        int b = idx & 63, jj = idx >> 6;
        float gi = sG[jj * GPAD + b];
        float gf = sG[(16 + jj) * GPAD + b];
        float gg = sG[(32 + jj) * GPAD + b];
        float go = sG[(48 + jj) * GPAD + b];
        float c = sgm(gf) * cst[e] + sgm(gi) * tanhf(gg);
        cst[e] = c;
        int j = ct * 16 + jj;
        unsigned off = (unsigned)((j & 127) * 128 + b * 2);
        off ^= (off >> 3) & 0x70;
        *reinterpret_cast<__half*>(panel + (size_t)(j >> 7) * 16384 + off) =
            __float2half_rn(sgm(go) * tanhf(c));
    }
}

// ------------------------------- main kernel -------------------------------
__global__ void __launch_bounds__(THRM, 1)
lstm_main(const float* __restrict__ c0) {
    extern __shared__ __align__(128) char smem[];
    float* sG = reinterpret_cast<float*>(smem + SG_OFF);
    const unsigned su = sptr(smem);

    const int tid = threadIdx.x, lane = tid & 31, wid = tid >> 5;
    const int ct = blockIdx.x;

    if (tid == 0)
        for (int s = 0; s < 4; s++) mbar_init(su + MB_OFF + s * 8, 1);
    __syncthreads();

    float cst0[2], cst1[2];
#pragma unroll
    for (int e = 0; e < 2; e++) {
        int idx = tid + e * THRM;
        int b = idx & 63, j = ct * 16 + (idx >> 6);
        cst0[e] = c0[(size_t)b * Hd + j];
        cst1[e] = c0[(size_t)(Bd + b) * Hd + j];
    }

    const uint4* W0 = g_Wf + ((size_t)0 * NCTA + ct) * 32768;
    const uint4* W1 = g_Wf + ((size_t)1 * NCTA + ct) * 32768;
    const float* bias0 = &g_bias[0][ct][0];
    const float* bias1 = &g_bias[1][ct][0];
    unsigned target = 0;

    for (int t = 0; t < Td; t++) {
        const int p = t & 1;
        const char* X0  = (t == 0) ? g_Xz : g_H1all[t - 1];
        const char* Hp0 = g_H0[p ^ 1];
        gemm_gates(W0, X0, Hp0, smem, bias0, tid, lane, wid, (t * 2 + 0) * 32);
        pointwise(sG, cst0, g_H0[p], ct, tid);
        gridbar(target);

        const char* X1  = g_H0[p];
        const char* Hp1 = (t == 0) ? g_H1init : g_H1all[t - 1];
        gemm_gates(W1, X1, Hp1, smem, bias1, tid, lane, wid, (t * 2 + 1) * 32);
        pointwise(sG, cst1, g_H1all[t], ct, tid);
        gridbar(target);
    }
}

// -------------------- proj GEMM (off critical path) -------------------------
template <int KTOT>
__device__ __forceinline__ void gemm64_old(const __half* __restrict__ Wg,
                                           const char* __restrict__ Xg,
                                           __half* sW, __half* sA, float* sG,
                                           const float* __restrict__ bias,
                                           int tid, int lane, int wid) {
    constexpr int NCHUNK = KTOT / KC;
    float acc[4][4];
#pragma unroll
    for (int i = 0; i < 4; i++)
#pragma unroll
        for (int j = 0; j < 4; j++) acc[i][j] = 0.f;
    const int wm = wid >> 1, wn = wid & 1;

    uint4 wr[4], ar[4];
#pragma unroll
    for (int i = 0; i < 4; i++) {
        int s = tid + i * THRP;
        wr[i] = *reinterpret_cast<const uint4*>(Wg + (size_t)(s >> 4) * KTOT + (s & 15) * 8);
    }
#pragma unroll
    for (int i = 0; i < 4; i++) {
        int s = tid + i * THRP;
        ar[i] = ld_act(Xg, s >> 3, (s & 7) * 8);
    }

#pragma unroll 1
    for (int kc = 0; kc < NCHUNK; kc++) {
        __half* sWc = sW + (kc & 1) * 64 * WPAD;
        __half* sAc = sA + (kc & 1) * KC * APAD;
#pragma unroll
        for (int i = 0; i < 4; i++) {
            int s = tid + i * THRP;
            *reinterpret_cast<uint4*>(sWc + (s >> 4) * WPAD + (s & 15) * 8) = wr[i];
        }
#pragma unroll
        for (int i = 0; i < 4; i++) {
            int s = tid + i * THRP;
            *reinterpret_cast<uint4*>(sAc + (s >> 3) * APAD + (s & 7) * 8) = ar[i];
        }
        __syncthreads();

        if (kc + 1 < NCHUNK) {
            int k0 = (kc + 1) * KC;
#pragma unroll
            for (int i = 0; i < 4; i++) {
                int s = tid + i * THRP;
                wr[i] = *reinterpret_cast<const uint4*>(
                    Wg + (size_t)(s >> 4) * KTOT + k0 + (s & 15) * 8);
            }
#pragma unroll
            for (int i = 0; i < 4; i++) {
                int s = tid + i * THRP;
                ar[i] = ld_act(Xg, k0 + (s >> 3), (s & 7) * 8);
            }
        }

        unsigned aBase = sptr(sWc + (wm * 16 + (lane & 15)) * WPAD + (lane >> 4) * 8);
        unsigned bBase = sptr(sAc + (lane & 15) * APAD + wn * 32 + (lane >> 4) * 8);
#pragma unroll
        for (int kk = 0; kk < KC / 16; kk++) {
            unsigned a0, a1, a2, a3;
            ldsm4(a0, a1, a2, a3, aBase + kk * 32);
#pragma unroll
            for (int nb2 = 0; nb2 < 2; nb2++) {
                unsigned b0, b1, b2, b3;
                ldsm4t(b0, b1, b2, b3,
                       bBase + (unsigned)((kk * 16 * APAD + nb2 * 16) * 2));
                mma16816(acc[nb2 * 2 + 0], a0, a1, a2, a3, b0, b1);
                mma16816(acc[nb2 * 2 + 1], a0, a1, a2, a3, b2, b3);
            }
        }
        __syncthreads();
    }

    {
        int rbase = wm * 16 + (lane >> 2);
        float bs0 = bias[rbase], bs1 = bias[rbase + 8];
#pragma unroll
        for (int nb = 0; nb < 4; nb++) {
            int cb = wn * 32 + nb * 8 + (lane & 3) * 2;
            sG[rbase * GPAD + cb]           = acc[nb][0] + bs0;
            sG[rbase * GPAD + cb + 1]       = acc[nb][1] + bs0;
            sG[(rbase + 8) * GPAD + cb]     = acc[nb][2] + bs1;
            sG[(rbase + 8) * GPAD + cb + 1] = acc[nb][3] + bs1;
        }
    }
    __syncthreads();
}

__global__ void __launch_bounds__(THRP)
proj_kernel(float* __restrict__ out) {
    extern __shared__ char smem[];
    __half* sW = reinterpret_cast<__half*>(smem);
    __half* sA = reinterpret_cast<__half*>(smem + SMEM_W_OLD);
    float*  sG = reinterpret_cast<float*>(smem + SMEM_W_OLD + SMEM_A_OLD);

    const int tid = threadIdx.x, lane = tid & 31, wid = tid >> 5;
    const int bx = blockIdx.x;
    const int t  = blockIdx.y;

    gemm64_old<Hd>(&g_WoutH[bx * 64][0], g_H1all[t],
                   sW, sA, sG, &g_bout[bx * 64], tid, lane, wid);

#pragma unroll
    for (int e = 0; e < 16; e++) {
        int idx = tid + e * THRP;
        int b = idx >> 6, oo = idx & 63;
        out[((size_t)(t * Bd + b)) * OUTD + bx * 64 + oo] = sG[oo * GPAD + b];
    }
}

// ------------------------------- entry point -------------------------------
extern "C" void kernel_launch(void* const* d_in, const int* in_sizes, int n_in,
                              void* d_out, int out_size) {
    const float* h0   = (const float*)d_in[0];
    const float* c0   = (const float*)d_in[1];
    const float* Wih  = (const float*)d_in[2];
    const float* Whh  = (const float*)d_in[3];
    const float* bih  = (const float*)d_in[4];
    const float* bhh  = (const float*)d_in[5];
    const float* Wout = (const float*)d_in[6];
    const float* bout = (const float*)d_in[7];
    float* out = (float*)d_out;

    cudaFuncSetAttribute(lstm_main, cudaFuncAttributeMaxDynamicSharedMemorySize, SMEM_MAIN);
    cudaFuncSetAttribute(proj_kernel, cudaFuncAttributeMaxDynamicSharedMemorySize, SMEM_PROJ);

    pack_w_kernel<<<32768, 256>>>(Wih, Whh);
    pack_wout_kernel<<<2048, 256>>>(Wout);
    pack_misc_kernel<<<512, 256>>>(h0, bih, bhh, bout);  // also resets g_count
    lstm_main<<<NCTA, THRM, SMEM_MAIN>>>(c0);
    proj_kernel<<<dim3(16, Td), THRP, SMEM_PROJ>>>(out);
}